// round 1
// baseline (speedup 1.0000x reference)
#include <cuda_runtime.h>

// Problem constants
#define B_  2
#define L_  64
#define D_  1024
#define H_  512
#define S_  50000
#define V_  40000
#define K_  32
#define M_  128            // B*L rows
#define SLM_SCALE 0.1f
#define BN_EPS 1e-5f

// ---------------- scratch (device globals; no allocation allowed) ----------
__device__ float g_scale[L_];
__device__ float g_shift[L_];
__device__ float g_h[M_ * H_];                 // 256 KB, L2-resident
__device__ float g_vT[(size_t)V_ * M_];        // 20.48 MB, v transposed [V][128]

// ---------------- helpers: packed f32x2 FMA (Blackwell FFMA2) --------------
__device__ __forceinline__ unsigned long long dup2(float v) {
    unsigned long long r;
    asm("mov.b64 %0, {%1, %1};" : "=l"(r) : "f"(v));
    return r;
}
__device__ __forceinline__ void ffma2(unsigned long long& d,
                                      unsigned long long a,
                                      unsigned long long b) {
    asm("fma.rn.f32x2 %0, %1, %2, %0;" : "+l"(d) : "l"(a), "l"(b));
}
__device__ __forceinline__ float2 unpack2(unsigned long long v) {
    float lo, hi;
    asm("mov.b64 {%0, %1}, %2;" : "=f"(lo), "=f"(hi) : "l"(v));
    return make_float2(lo, hi);
}

// ---------------- kernel 1: BN stats per channel l --------------------------
__global__ void bn_stats_kernel(const float* __restrict__ x,
                                const float* __restrict__ gamma,
                                const float* __restrict__ beta) {
    int l = blockIdx.x;
    int tid = threadIdx.x;
    const float* r0 = x + (size_t)l * D_;          // b = 0
    const float* r1 = x + (size_t)(L_ + l) * D_;   // b = 1
    float s = 0.f, ss = 0.f;
    for (int d = tid; d < D_; d += blockDim.x) {
        float a = r0[d], b = r1[d];
        s  += a + b;
        ss += a * a + b * b;
    }
    __shared__ float sh_s[8], sh_ss[8];
    #pragma unroll
    for (int o = 16; o; o >>= 1) {
        s  += __shfl_down_sync(0xffffffffu, s,  o);
        ss += __shfl_down_sync(0xffffffffu, ss, o);
    }
    int w = tid >> 5;
    if ((tid & 31) == 0) { sh_s[w] = s; sh_ss[w] = ss; }
    __syncthreads();
    if (tid == 0) {
        float S = 0.f, SS = 0.f;
        #pragma unroll
        for (int i = 0; i < 8; i++) { S += sh_s[i]; SS += sh_ss[i]; }
        float inv_n = 1.0f / (2.0f * D_);
        float mean = S * inv_n;
        float var  = SS * inv_n - mean * mean;
        float sc = gamma[l] * rsqrtf(var + BN_EPS);
        g_scale[l] = sc;
        g_shift[l] = beta[l] - mean * sc;
    }
}

// ---------------- kernel 2: h = relu(xn @ W1 + b1) --------------------------
// One block per l (both batches share scale/shift); 512 threads = one j each.
__global__ void h_kernel(const float* __restrict__ x,
                         const float* __restrict__ W1,
                         const float* __restrict__ b1) {
    int l = blockIdx.x;
    int j = threadIdx.x;   // 0..511
    __shared__ float xs0[D_];
    __shared__ float xs1[D_];
    float sc = g_scale[l], sh = g_shift[l];
    const float* r0 = x + (size_t)l * D_;
    const float* r1 = x + (size_t)(L_ + l) * D_;
    for (int d = j; d < D_; d += blockDim.x) {
        xs0[d] = r0[d] * sc + sh;
        xs1[d] = r1[d] * sc + sh;
    }
    __syncthreads();
    float a0 = b1[j], a1 = a0;
    #pragma unroll 8
    for (int d = 0; d < D_; d++) {
        float w = W1[(size_t)d * H_ + j];
        a0 += xs0[d] * w;
        a1 += xs1[d] * w;
    }
    g_h[(size_t)l * H_ + j]        = fmaxf(a0, 0.f);
    g_h[(size_t)(L_ + l) * H_ + j] = fmaxf(a1, 0.f);
}

// ---------------- kernel 3: C[128,N] = h @ W + bias -------------------------
// MODE 0: store row-major to outp (y).  MODE 1: store transposed fp32 to g_vT.
// Block tile: 128(M) x 64(N), Kc = 16. 256 threads, per-thread 8x4 micro-tile
// computed as 4 m-pairs x 4 n using packed f32x2 FMA.
template <int MODE>
__global__ void __launch_bounds__(256)
gemm_kernel(const float* __restrict__ Wmat,
            const float* __restrict__ bias,
            float* __restrict__ outp, int N) {
    const int KC = 16;
    __shared__ float As[KC][132];   // As[k][m], padded
    __shared__ float Bs[KC][68];    // Bs[k][n], padded

    int tid = threadIdx.x;
    int tx = tid & 15;        // n group
    int ty = tid >> 4;        // m group
    int n0 = blockIdx.x * 64;

    unsigned long long acc[4][4];
    #pragma unroll
    for (int i = 0; i < 4; i++)
        #pragma unroll
        for (int jn = 0; jn < 4; jn++) acc[i][jn] = 0ull;

    for (int k0 = 0; k0 < H_; k0 += KC) {
        // stage A chunk: As[k][m] = h[m][k0+k]
        #pragma unroll
        for (int i = 0; i < 2; i++) {
            int q = tid + i * 256;       // 0..511
            int m  = q >> 2;
            int kq = q & 3;
            float4 v = *reinterpret_cast<const float4*>(
                &g_h[(size_t)m * H_ + k0 + kq * 4]);
            As[kq * 4 + 0][m] = v.x;
            As[kq * 4 + 1][m] = v.y;
            As[kq * 4 + 2][m] = v.z;
            As[kq * 4 + 3][m] = v.w;
        }
        // stage B chunk: Bs[k][n] = W[k0+k][n0+n]
        {
            int k  = tid >> 4;
            int nq = tid & 15;
            int col = n0 + nq * 4;
            float4 v = make_float4(0.f, 0.f, 0.f, 0.f);
            if (col < N)   // N % 4 == 0 so col<N implies col+3<N
                v = *reinterpret_cast<const float4*>(
                        Wmat + (size_t)(k0 + k) * N + col);
            Bs[k][nq * 4 + 0] = v.x;
            Bs[k][nq * 4 + 1] = v.y;
            Bs[k][nq * 4 + 2] = v.z;
            Bs[k][nq * 4 + 3] = v.w;
        }
        __syncthreads();
        #pragma unroll
        for (int k = 0; k < KC; k++) {
            ulonglong2 aA = *reinterpret_cast<const ulonglong2*>(&As[k][ty * 8]);
            ulonglong2 aB = *reinterpret_cast<const ulonglong2*>(&As[k][ty * 8 + 4]);
            unsigned long long a[4] = {aA.x, aA.y, aB.x, aB.y};
            float4 b4 = *reinterpret_cast<const float4*>(&Bs[k][tx * 4]);
            unsigned long long bd[4] = {dup2(b4.x), dup2(b4.y), dup2(b4.z), dup2(b4.w)};
            #pragma unroll
            for (int mp = 0; mp < 4; mp++)
                #pragma unroll
                for (int n = 0; n < 4; n++)
                    ffma2(acc[mp][n], a[mp], bd[n]);
        }
        __syncthreads();
    }

    // epilogue
    #pragma unroll
    for (int n = 0; n < 4; n++) {
        int col = n0 + tx * 4 + n;
        if (col >= N) continue;
        float bv = bias[col];
        #pragma unroll
        for (int mp = 0; mp < 4; mp++) {
            float2 c = unpack2(acc[mp][n]);
            int m = ty * 8 + mp * 2;
            if (MODE == 0) {
                outp[(size_t)m * N + col]       = c.x + bv;
                outp[(size_t)(m + 1) * N + col] = c.y + bv;
            } else {
                *reinterpret_cast<float2*>(&g_vT[(size_t)col * M_ + m]) =
                    make_float2(c.x + bv, c.y + bv);
            }
        }
    }
}

// ---------------- kernel 4: out += SLM_SCALE * gather-sum -------------------
// Block = 128 threads (one per row), handles GTS=32 sense columns.
// Each index lookup reads a contiguous 512B row of g_vT serving all 128 rows.
#define GTS 32
__global__ void __launch_bounds__(128)
gather_add_kernel(const int* __restrict__ sl_idx,
                  const float* __restrict__ sl_w,
                  float* __restrict__ outp) {
    __shared__ int   sidx[GTS * K_];
    __shared__ float swt [GTS * K_];
    __shared__ float sout[M_ * (GTS + 1)];

    int tid = threadIdx.x;        // row
    int s0 = blockIdx.x * GTS;

    // stage indices + weights (contiguous [S][32] rows)
    for (int e = tid; e < GTS * K_; e += 128) {
        size_t g = (size_t)s0 * K_ + e;
        bool ok = (s0 + e / K_) < S_;
        sidx[e] = ok ? sl_idx[g] : 0;
        swt[e]  = ok ? sl_w[g]   : 0.f;
    }
    __syncthreads();

    for (int s = 0; s < GTS; s++) {
        float a0 = 0.f, a1 = 0.f, a2 = 0.f, a3 = 0.f;
        const int*   ip = &sidx[s * K_];
        const float* wp = &swt [s * K_];
        #pragma unroll
        for (int k = 0; k < K_; k += 4) {
            a0 += wp[k + 0] * g_vT[(size_t)ip[k + 0] * M_ + tid];
            a1 += wp[k + 1] * g_vT[(size_t)ip[k + 1] * M_ + tid];
            a2 += wp[k + 2] * g_vT[(size_t)ip[k + 2] * M_ + tid];
            a3 += wp[k + 3] * g_vT[(size_t)ip[k + 3] * M_ + tid];
        }
        sout[tid * (GTS + 1) + s] = (a0 + a1) + (a2 + a3);
    }
    __syncthreads();

    // coalesced read-modify-write of out: warp w handles rows w, w+4, ...
    int warp = tid >> 5, lane = tid & 31;
    for (int r = warp; r < M_; r += 4) {
        int s = s0 + lane;
        if (s < S_) {
            size_t o = (size_t)r * S_ + s;
            outp[o] += SLM_SCALE * sout[r * (GTS + 1) + lane];
        }
    }
}

// ---------------- launch ----------------------------------------------------
extern "C" void kernel_launch(void* const* d_in, const int* in_sizes, int n_in,
                              void* d_out, int out_size) {
    const float* x     = (const float*)d_in[0];
    const float* gamma = (const float*)d_in[1];
    const float* beta  = (const float*)d_in[2];
    const float* W1    = (const float*)d_in[3];
    const float* b1    = (const float*)d_in[4];
    const float* W2    = (const float*)d_in[5];
    const float* b2    = (const float*)d_in[6];
    const float* Wslm  = (const float*)d_in[7];
    const float* bslm  = (const float*)d_in[8];
    const float* slw   = (const float*)d_in[9];
    const int*   sli   = (const int*)d_in[10];
    float* out = (float*)d_out;

    bn_stats_kernel<<<L_, 256>>>(x, gamma, beta);
    h_kernel<<<L_, 512>>>(x, W1, b1);
    gemm_kernel<0><<<(S_ + 63) / 64, 256>>>(W2, b2, out, S_);
    gemm_kernel<1><<<V_ / 64, 256>>>(Wslm, bslm, nullptr, V_);
    gather_add_kernel<<<(S_ + GTS - 1) / GTS, 128>>>(sli, slw, out);
}

// round 5
// speedup vs baseline: 1.8067x; 1.8067x over previous
#include <cuda_runtime.h>
#include <cstdint>

// Problem constants
#define B_  2
#define L_  64
#define D_  1024
#define H_  512
#define S_  50000
#define V_  40000
#define K_  32
#define M_  128            // B*L rows
#define SLM_SCALE 0.1f
#define BN_EPS 1e-5f

// ---------------- scratch (device globals; no allocation allowed) ----------
__device__ float g_scale[L_];
__device__ float g_shift[L_];
__device__ float g_h[M_ * H_];                 // 256 KB, tf32-rounded
__device__ float g_vT[(size_t)V_ * M_];        // 20.48 MB, v transposed [V][128]

// ---------------- helpers ---------------------------------------------------
__device__ __forceinline__ uint32_t smem_u32(const void* p) {
    uint32_t a;
    asm("{ .reg .u64 t; cvta.to.shared.u64 t, %1; cvt.u32.u64 %0, t; }"
        : "=r"(a) : "l"(p));
    return a;
}
__device__ __forceinline__ float rna_tf32(float x) {
    uint32_t r;
    asm("cvt.rna.tf32.f32 %0, %1;" : "=r"(r) : "f"(x));
    return __uint_as_float(r);
}
__device__ __forceinline__ uint32_t rna_tf32_u(float x) {
    uint32_t r;
    asm("cvt.rna.tf32.f32 %0, %1;" : "=r"(r) : "f"(x));
    return r;
}
__device__ __forceinline__ void cp16(uint32_t dst, const void* src) {
    asm volatile("cp.async.cg.shared.global [%0], [%1], 16;"
                 :: "r"(dst), "l"(src));
}
__device__ __forceinline__ void cp16z(uint32_t dst, const void* src, int sz) {
    asm volatile("cp.async.cg.shared.global [%0], [%1], 16, %2;"
                 :: "r"(dst), "l"(src), "r"(sz));
}
__device__ __forceinline__ void mma_tf32(float& c0, float& c1, float& c2, float& c3,
                                         uint32_t a0, uint32_t a1, uint32_t a2, uint32_t a3,
                                         uint32_t b0, uint32_t b1) {
    asm volatile("mma.sync.aligned.m16n8k8.row.col.f32.tf32.tf32.f32 "
                 "{%0,%1,%2,%3}, {%4,%5,%6,%7}, {%8,%9}, {%0,%1,%2,%3};"
                 : "+f"(c0), "+f"(c1), "+f"(c2), "+f"(c3)
                 : "r"(a0), "r"(a1), "r"(a2), "r"(a3), "r"(b0), "r"(b1));
}

// ---------------- kernel 1: BN stats per channel l --------------------------
__global__ void bn_stats_kernel(const float* __restrict__ x,
                                const float* __restrict__ gamma,
                                const float* __restrict__ beta) {
    int l = blockIdx.x;
    int tid = threadIdx.x;
    const float* r0 = x + (size_t)l * D_;
    const float* r1 = x + (size_t)(L_ + l) * D_;
    float s = 0.f, ss = 0.f;
    for (int d = tid; d < D_; d += blockDim.x) {
        float a = r0[d], b = r1[d];
        s  += a + b;
        ss += a * a + b * b;
    }
    __shared__ float sh_s[8], sh_ss[8];
    #pragma unroll
    for (int o = 16; o; o >>= 1) {
        s  += __shfl_down_sync(0xffffffffu, s,  o);
        ss += __shfl_down_sync(0xffffffffu, ss, o);
    }
    int w = tid >> 5;
    if ((tid & 31) == 0) { sh_s[w] = s; sh_ss[w] = ss; }
    __syncthreads();
    if (tid == 0) {
        float S = 0.f, SS = 0.f;
        #pragma unroll
        for (int i = 0; i < 8; i++) { S += sh_s[i]; SS += sh_ss[i]; }
        float inv_n = 1.0f / (2.0f * D_);
        float mean = S * inv_n;
        float var  = SS * inv_n - mean * mean;
        float sc = gamma[l] * rsqrtf(var + BN_EPS);
        g_scale[l] = sc;
        g_shift[l] = beta[l] - mean * sc;
    }
}

// ---------------- kernel 2: h = relu(xn @ W1 + b1), tf32-rounded ------------
__global__ void h_kernel(const float* __restrict__ x,
                         const float* __restrict__ W1,
                         const float* __restrict__ b1) {
    int l = blockIdx.x;
    int j = threadIdx.x;   // 0..511
    __shared__ float xs0[D_];
    __shared__ float xs1[D_];
    float sc = g_scale[l], sh = g_shift[l];
    const float* r0 = x + (size_t)l * D_;
    const float* r1 = x + (size_t)(L_ + l) * D_;
    for (int d = j; d < D_; d += blockDim.x) {
        xs0[d] = r0[d] * sc + sh;
        xs1[d] = r1[d] * sc + sh;
    }
    __syncthreads();
    float a0 = b1[j], a1 = a0;
    #pragma unroll 8
    for (int d = 0; d < D_; d++) {
        float w = W1[(size_t)d * H_ + j];
        a0 += xs0[d] * w;
        a1 += xs1[d] * w;
    }
    g_h[(size_t)l * H_ + j]        = rna_tf32(fmaxf(a0, 0.f));
    g_h[(size_t)(L_ + l) * H_ + j] = rna_tf32(fmaxf(a1, 0.f));
}

// ---------------- kernel 3: mma.sync tf32 GEMM C[128,N] = h @ W + bias ------
// MODE 0: row-major to outp (y).  MODE 1: transposed (via smem) to g_vT.
// CTA: 256 threads = 8 warps in 2(m) x 4(n); warp tile 64x32 of m16n8k8 frags.
// K-chunks of 32, double-buffered cp.async.
#define NBLK 128
#define KC   32
#define SA   36                 // A smem stride (floats): banks (4g+tig) distinct
#define SBr  136                // B smem stride (floats): banks (8tig+g) distinct
#define A_SZ (128 * SA)         // 4608 floats
#define B_SZ (KC * SBr)         // 4352 floats
#define GEMM_SMEM ((2 * (A_SZ + B_SZ)) * 4)   // 71680 bytes
#define SC   132                // C transpose stride (floats)

template <int MODE>
__global__ void __launch_bounds__(256, 2)
gemm_mma_kernel(const float* __restrict__ Wmat,
                const float* __restrict__ bias,
                float* __restrict__ outp, int N) {
    extern __shared__ float smem[];
    const uint32_t sbase = smem_u32(smem);

    int tid  = threadIdx.x;
    int wid  = tid >> 5, lane = tid & 31;
    int mw   = wid >> 2;          // 0..1  (64-row half)
    int nw   = wid & 3;           // 0..3  (32-col quarter)
    int g    = lane >> 2;         // 0..7
    int tig  = lane & 3;          // 0..3
    int n0   = blockIdx.x * NBLK;

    float c[4][4][4];
    #pragma unroll
    for (int mf = 0; mf < 4; mf++)
        #pragma unroll
        for (int nf = 0; nf < 4; nf++)
            #pragma unroll
            for (int i = 0; i < 4; i++) c[mf][nf][i] = 0.f;

    // ---- staging helper (A: 4 chunks, B: 4 chunks of 16B per thread) ----
    auto stage = [&](int it, int buf) {
        int k0 = it * KC;
        uint32_t a_s = sbase + (uint32_t)(buf * A_SZ) * 4u;
        uint32_t b_s = sbase + (uint32_t)(2 * A_SZ + buf * B_SZ) * 4u;
        #pragma unroll
        for (int i = 0; i < 4; i++) {
            int q = tid + i * 256;               // 0..1023
            int row = q >> 3, c4 = q & 7;
            cp16(a_s + (uint32_t)(row * SA + c4 * 4) * 4u,
                 &g_h[(size_t)row * H_ + k0 + c4 * 4]);
        }
        #pragma unroll
        for (int i = 0; i < 4; i++) {
            int q = tid + i * 256;               // 0..1023
            int kr = q >> 5, c4 = q & 31;
            int col = n0 + c4 * 4;
            cp16z(b_s + (uint32_t)(kr * SBr + c4 * 4) * 4u,
                  Wmat + (size_t)(k0 + kr) * N + col,
                  (col < N) ? 16 : 0);           // N % 4 == 0
        }
    };

    stage(0, 0);
    asm volatile("cp.async.commit_group;" ::: "memory");

    const int ITER = H_ / KC;                    // 16
    for (int it = 0; it < ITER; ++it) {
        int buf = it & 1;
        if (it + 1 < ITER) {
            stage(it + 1, buf ^ 1);
            asm volatile("cp.async.commit_group;" ::: "memory");
            asm volatile("cp.async.wait_group 1;" ::: "memory");
        } else {
            asm volatile("cp.async.wait_group 0;" ::: "memory");
        }
        __syncthreads();

        const float* Af = smem + buf * A_SZ;
        const float* Bf = smem + 2 * A_SZ + buf * B_SZ;

        #pragma unroll
        for (int ks = 0; ks < 4; ks++) {
            uint32_t a[4][4], b[4][2];
            int kc = ks * 8 + tig;
            #pragma unroll
            for (int mf = 0; mf < 4; mf++) {
                int r = mw * 64 + mf * 16 + g;
                a[mf][0] = __float_as_uint(Af[r * SA + kc]);
                a[mf][1] = __float_as_uint(Af[(r + 8) * SA + kc]);
                a[mf][2] = __float_as_uint(Af[r * SA + kc + 4]);
                a[mf][3] = __float_as_uint(Af[(r + 8) * SA + kc + 4]);
            }
            #pragma unroll
            for (int nf = 0; nf < 4; nf++) {
                int ncol = nw * 32 + nf * 8 + g;
                b[nf][0] = rna_tf32_u(Bf[kc * SBr + ncol]);
                b[nf][1] = rna_tf32_u(Bf[(kc + 4) * SBr + ncol]);
            }
            #pragma unroll
            for (int mf = 0; mf < 4; mf++)
                #pragma unroll
                for (int nf = 0; nf < 4; nf++)
                    mma_tf32(c[mf][nf][0], c[mf][nf][1], c[mf][nf][2], c[mf][nf][3],
                             a[mf][0], a[mf][1], a[mf][2], a[mf][3],
                             b[nf][0], b[nf][1]);
        }
        __syncthreads();
    }

    if (MODE == 0) {
        // direct row-major stores: c0/c1 at (row, col..col+1), c2/c3 at row+8
        #pragma unroll
        for (int mf = 0; mf < 4; mf++) {
            int row = mw * 64 + mf * 16 + g;
            #pragma unroll
            for (int nf = 0; nf < 4; nf++) {
                int col = n0 + nw * 32 + nf * 8 + 2 * tig;
                if (col < N) {      // col even, N even -> col+1 < N
                    float bv0 = bias[col], bv1 = bias[col + 1];
                    *reinterpret_cast<float2*>(&outp[(size_t)row * N + col]) =
                        make_float2(c[mf][nf][0] + bv0, c[mf][nf][1] + bv1);
                    *reinterpret_cast<float2*>(&outp[(size_t)(row + 8) * N + col]) =
                        make_float2(c[mf][nf][2] + bv0, c[mf][nf][3] + bv1);
                }
            }
        }
    } else {
        // transpose through smem (buffers are free now), then coalesced rows
        float* Cs = smem;
        #pragma unroll
        for (int mf = 0; mf < 4; mf++) {
            int m = mw * 64 + mf * 16 + g;
            #pragma unroll
            for (int nf = 0; nf < 4; nf++) {
                int ncol = nw * 32 + nf * 8 + 2 * tig;
                Cs[ncol * SC + m]           = c[mf][nf][0];
                Cs[(ncol + 1) * SC + m]     = c[mf][nf][1];
                Cs[ncol * SC + m + 8]       = c[mf][nf][2];
                Cs[(ncol + 1) * SC + m + 8] = c[mf][nf][3];
            }
        }
        __syncthreads();
        #pragma unroll
        for (int i = 0; i < 16; i++) {
            int q = tid + i * 256;           // 0..4095
            int nrow = q >> 5, m4 = (q & 31) * 4;
            int col = n0 + nrow;
            if (col < N) {
                float bv = bias[col];
                float4 v = *reinterpret_cast<const float4*>(&Cs[nrow * SC + m4]);
                v.x += bv; v.y += bv; v.z += bv; v.w += bv;
                *reinterpret_cast<float4*>(&g_vT[(size_t)col * M_ + m4]) = v;
            }
        }
    }
}

// ---------------- kernel 4: out += SLM_SCALE * gather-sum -------------------
#define GTS 32
__global__ void __launch_bounds__(128)
gather_add_kernel(const int* __restrict__ sl_idx,
                  const float* __restrict__ sl_w,
                  float* __restrict__ outp) {
    __shared__ int   sidx[GTS * K_];
    __shared__ float swt [GTS * K_];
    __shared__ float sout[M_ * (GTS + 1)];

    int tid = threadIdx.x;        // row
    int s0 = blockIdx.x * GTS;

    for (int e = tid; e < GTS * K_; e += 128) {
        size_t gg = (size_t)s0 * K_ + e;
        bool ok = (s0 + e / K_) < S_;
        sidx[e] = ok ? sl_idx[gg] : 0;
        swt[e]  = ok ? sl_w[gg]   : 0.f;
    }
    __syncthreads();

    for (int s = 0; s < GTS; s++) {
        float a0 = 0.f, a1 = 0.f, a2 = 0.f, a3 = 0.f;
        const int*   ip = &sidx[s * K_];
        const float* wp = &swt [s * K_];
        #pragma unroll
        for (int k = 0; k < K_; k += 4) {
            a0 += wp[k + 0] * g_vT[(size_t)ip[k + 0] * M_ + tid];
            a1 += wp[k + 1] * g_vT[(size_t)ip[k + 1] * M_ + tid];
            a2 += wp[k + 2] * g_vT[(size_t)ip[k + 2] * M_ + tid];
            a3 += wp[k + 3] * g_vT[(size_t)ip[k + 3] * M_ + tid];
        }
        sout[tid * (GTS + 1) + s] = (a0 + a1) + (a2 + a3);
    }
    __syncthreads();

    int warp = tid >> 5, lane = tid & 31;
    for (int r = warp; r < M_; r += 4) {
        int s = s0 + lane;
        if (s < S_) {
            size_t o = (size_t)r * S_ + s;
            outp[o] += SLM_SCALE * sout[r * (GTS + 1) + lane];
        }
    }
}

// ---------------- launch ----------------------------------------------------
extern "C" void kernel_launch(void* const* d_in, const int* in_sizes, int n_in,
                              void* d_out, int out_size) {
    const float* x     = (const float*)d_in[0];
    const float* gamma = (const float*)d_in[1];
    const float* beta  = (const float*)d_in[2];
    const float* W1    = (const float*)d_in[3];
    const float* b1    = (const float*)d_in[4];
    const float* W2    = (const float*)d_in[5];
    const float* b2    = (const float*)d_in[6];
    const float* Wslm  = (const float*)d_in[7];
    const float* bslm  = (const float*)d_in[8];
    const float* slw   = (const float*)d_in[9];
    const int*   sli   = (const int*)d_in[10];
    float* out = (float*)d_out;

    static int smem_set = 0;
    if (!smem_set) {
        cudaFuncSetAttribute(gemm_mma_kernel<0>,
                             cudaFuncAttributeMaxDynamicSharedMemorySize, GEMM_SMEM);
        cudaFuncSetAttribute(gemm_mma_kernel<1>,
                             cudaFuncAttributeMaxDynamicSharedMemorySize, GEMM_SMEM);
        smem_set = 1;
    }

    bn_stats_kernel<<<L_, 256>>>(x, gamma, beta);
    h_kernel<<<L_, 512>>>(x, W1, b1);
    gemm_mma_kernel<1><<<(V_ + NBLK - 1) / NBLK, 256, GEMM_SMEM>>>(Wslm, bslm, nullptr, V_);
    gemm_mma_kernel<0><<<(S_ + NBLK - 1) / NBLK, 256, GEMM_SMEM>>>(W2, b2, out, S_);
    gather_add_kernel<<<(S_ + GTS - 1) / GTS, 128>>>(sli, slw, out);
}

// round 6
// speedup vs baseline: 2.0492x; 1.1342x over previous
#include <cuda_runtime.h>
#include <cstdint>

// Problem constants
#define B_  2
#define L_  64
#define D_  1024
#define H_  512
#define S_  50000
#define V_  40000
#define K_  32
#define M_  128            // B*L rows
#define SLM_SCALE 0.1f
#define BN_EPS 1e-5f

// ---------------- scratch (device globals; no allocation allowed) ----------
__device__ float g_scale[L_];
__device__ float g_shift[L_];
__device__ float g_h[M_ * H_];                    // 256 KB, tf32-rounded
__device__ uint32_t g_vT2[(size_t)V_ * 64];       // 10.24 MB, v [V][128] as bf16x2

// ---------------- helpers ---------------------------------------------------
__device__ __forceinline__ uint32_t smem_u32(const void* p) {
    uint32_t a;
    asm("{ .reg .u64 t; cvta.to.shared.u64 t, %1; cvt.u32.u64 %0, t; }"
        : "=r"(a) : "l"(p));
    return a;
}
__device__ __forceinline__ float rna_tf32(float x) {
    uint32_t r;
    asm("cvt.rna.tf32.f32 %0, %1;" : "=r"(r) : "f"(x));
    return __uint_as_float(r);
}
__device__ __forceinline__ uint32_t rna_tf32_u(float x) {
    uint32_t r;
    asm("cvt.rna.tf32.f32 %0, %1;" : "=r"(r) : "f"(x));
    return r;
}
__device__ __forceinline__ uint32_t pack_bf16(float hi, float lo) {
    uint32_t r;
    asm("cvt.rn.bf16x2.f32 %0, %1, %2;" : "=r"(r) : "f"(hi), "f"(lo));
    return r;
}
__device__ __forceinline__ void cp16(uint32_t dst, const void* src) {
    asm volatile("cp.async.cg.shared.global [%0], [%1], 16;"
                 :: "r"(dst), "l"(src));
}
__device__ __forceinline__ void cp16z(uint32_t dst, const void* src, int sz) {
    asm volatile("cp.async.cg.shared.global [%0], [%1], 16, %2;"
                 :: "r"(dst), "l"(src), "r"(sz));
}
__device__ __forceinline__ void mma_tf32(float& c0, float& c1, float& c2, float& c3,
                                         uint32_t a0, uint32_t a1, uint32_t a2, uint32_t a3,
                                         uint32_t b0, uint32_t b1) {
    asm volatile("mma.sync.aligned.m16n8k8.row.col.f32.tf32.tf32.f32 "
                 "{%0,%1,%2,%3}, {%4,%5,%6,%7}, {%8,%9}, {%0,%1,%2,%3};"
                 : "+f"(c0), "+f"(c1), "+f"(c2), "+f"(c3)
                 : "r"(a0), "r"(a1), "r"(a2), "r"(a3), "r"(b0), "r"(b1));
}

// ---------------- kernel 1: BN stats per channel l --------------------------
__global__ void bn_stats_kernel(const float* __restrict__ x,
                                const float* __restrict__ gamma,
                                const float* __restrict__ beta) {
    int l = blockIdx.x;
    int tid = threadIdx.x;
    const float* r0 = x + (size_t)l * D_;
    const float* r1 = x + (size_t)(L_ + l) * D_;
    float s = 0.f, ss = 0.f;
    for (int d = tid; d < D_; d += blockDim.x) {
        float a = r0[d], b = r1[d];
        s  += a + b;
        ss += a * a + b * b;
    }
    __shared__ float sh_s[8], sh_ss[8];
    #pragma unroll
    for (int o = 16; o; o >>= 1) {
        s  += __shfl_down_sync(0xffffffffu, s,  o);
        ss += __shfl_down_sync(0xffffffffu, ss, o);
    }
    int w = tid >> 5;
    if ((tid & 31) == 0) { sh_s[w] = s; sh_ss[w] = ss; }
    __syncthreads();
    if (tid == 0) {
        float S = 0.f, SS = 0.f;
        #pragma unroll
        for (int i = 0; i < 8; i++) { S += sh_s[i]; SS += sh_ss[i]; }
        float inv_n = 1.0f / (2.0f * D_);
        float mean = S * inv_n;
        float var  = SS * inv_n - mean * mean;
        float sc = gamma[l] * rsqrtf(var + BN_EPS);
        g_scale[l] = sc;
        g_shift[l] = beta[l] - mean * sc;
    }
}

// ---------------- kernel 2: h = relu(xn @ W1 + b1), tf32-rounded ------------
__global__ void h_kernel(const float* __restrict__ x,
                         const float* __restrict__ W1,
                         const float* __restrict__ b1) {
    int l = blockIdx.x;
    int j = threadIdx.x;   // 0..511
    __shared__ float xs0[D_];
    __shared__ float xs1[D_];
    float sc = g_scale[l], sh = g_shift[l];
    const float* r0 = x + (size_t)l * D_;
    const float* r1 = x + (size_t)(L_ + l) * D_;
    for (int d = j; d < D_; d += blockDim.x) {
        xs0[d] = r0[d] * sc + sh;
        xs1[d] = r1[d] * sc + sh;
    }
    __syncthreads();
    float a0 = b1[j], a1 = a0;
    #pragma unroll 8
    for (int d = 0; d < D_; d++) {
        float w = W1[(size_t)d * H_ + j];
        a0 += xs0[d] * w;
        a1 += xs1[d] * w;
    }
    g_h[(size_t)l * H_ + j]        = rna_tf32(fmaxf(a0, 0.f));
    g_h[(size_t)(L_ + l) * H_ + j] = rna_tf32(fmaxf(a1, 0.f));
}

// ---------------- kernel 3: mma.sync tf32 GEMM C[128,N] = h @ W + bias ------
// MODE 0: row-major to outp (y).  MODE 1: bf16x2 transposed to g_vT2.
// CTA: 256 threads = 8 warps in 2(m) x 4(n); warp tile 64x32 of m16n8k8 frags.
// K-chunks of 32, 3-stage cp.async pipeline.
#define NBLK 128
#define KC   32
#define SA   36                 // A smem stride (floats)
#define SBr  136                // B smem stride (floats)
#define A_SZ (128 * SA)         // 4608 floats
#define B_SZ (KC * SBr)         // 4352 floats
#define STG  3
#define GEMM_SMEM ((STG * (A_SZ + B_SZ)) * 4)   // 107520 bytes
#define SC   132                // C transpose stride (floats)

template <int MODE>
__global__ void __launch_bounds__(256, 2)
gemm_mma_kernel(const float* __restrict__ Wmat,
                const float* __restrict__ bias,
                float* __restrict__ outp, int N) {
    extern __shared__ float smem[];
    const uint32_t sbase = smem_u32(smem);

    int tid  = threadIdx.x;
    int wid  = tid >> 5, lane = tid & 31;
    int mw   = wid >> 2;          // 0..1  (64-row half)
    int nw   = wid & 3;           // 0..3  (32-col quarter)
    int g    = lane >> 2;         // 0..7
    int tig  = lane & 3;          // 0..3
    int n0   = blockIdx.x * NBLK;

    float c[4][4][4];
    #pragma unroll
    for (int mf = 0; mf < 4; mf++)
        #pragma unroll
        for (int nf = 0; nf < 4; nf++)
            #pragma unroll
            for (int i = 0; i < 4; i++) c[mf][nf][i] = 0.f;

    auto stage = [&](int it, int buf) {
        int k0 = it * KC;
        uint32_t a_s = sbase + (uint32_t)(buf * (A_SZ + B_SZ)) * 4u;
        uint32_t b_s = a_s + (uint32_t)A_SZ * 4u;
        #pragma unroll
        for (int i = 0; i < 4; i++) {
            int q = tid + i * 256;               // 0..1023
            int row = q >> 3, c4 = q & 7;
            cp16(a_s + (uint32_t)(row * SA + c4 * 4) * 4u,
                 &g_h[(size_t)row * H_ + k0 + c4 * 4]);
        }
        #pragma unroll
        for (int i = 0; i < 4; i++) {
            int q = tid + i * 256;               // 0..1023
            int kr = q >> 5, c4 = q & 31;
            int col = n0 + c4 * 4;
            cp16z(b_s + (uint32_t)(kr * SBr + c4 * 4) * 4u,
                  Wmat + (size_t)(k0 + kr) * N + col,
                  (col < N) ? 16 : 0);           // N % 4 == 0
        }
    };

    const int ITER = H_ / KC;                    // 16
    stage(0, 0);
    asm volatile("cp.async.commit_group;" ::: "memory");
    stage(1, 1);
    asm volatile("cp.async.commit_group;" ::: "memory");

    for (int it = 0; it < ITER; ++it) {
        int buf = it % STG;
        if (it + 1 < ITER)
            asm volatile("cp.async.wait_group 1;" ::: "memory");
        else
            asm volatile("cp.async.wait_group 0;" ::: "memory");
        __syncthreads();

        const float* Af = smem + buf * (A_SZ + B_SZ);
        const float* Bf = Af + A_SZ;

        #pragma unroll
        for (int ks = 0; ks < 4; ks++) {
            uint32_t a[4][4], b[4][2];
            int kc = ks * 8 + tig;
            #pragma unroll
            for (int mf = 0; mf < 4; mf++) {
                int r = mw * 64 + mf * 16 + g;
                a[mf][0] = __float_as_uint(Af[r * SA + kc]);
                a[mf][1] = __float_as_uint(Af[(r + 8) * SA + kc]);
                a[mf][2] = __float_as_uint(Af[r * SA + kc + 4]);
                a[mf][3] = __float_as_uint(Af[(r + 8) * SA + kc + 4]);
            }
            #pragma unroll
            for (int nf = 0; nf < 4; nf++) {
                int ncol = nw * 32 + nf * 8 + g;
                b[nf][0] = rna_tf32_u(Bf[kc * SBr + ncol]);
                b[nf][1] = rna_tf32_u(Bf[(kc + 4) * SBr + ncol]);
            }
            #pragma unroll
            for (int mf = 0; mf < 4; mf++)
                #pragma unroll
                for (int nf = 0; nf < 4; nf++)
                    mma_tf32(c[mf][nf][0], c[mf][nf][1], c[mf][nf][2], c[mf][nf][3],
                             a[mf][0], a[mf][1], a[mf][2], a[mf][3],
                             b[nf][0], b[nf][1]);
        }
        __syncthreads();
        if (it + 2 < ITER) {
            stage(it + 2, (it + 2) % STG);
            asm volatile("cp.async.commit_group;" ::: "memory");
        }
    }

    if (MODE == 0) {
        #pragma unroll
        for (int mf = 0; mf < 4; mf++) {
            int row = mw * 64 + mf * 16 + g;
            #pragma unroll
            for (int nf = 0; nf < 4; nf++) {
                int col = n0 + nw * 32 + nf * 8 + 2 * tig;
                if (col < N) {
                    float bv0 = bias[col], bv1 = bias[col + 1];
                    *reinterpret_cast<float2*>(&outp[(size_t)row * N + col]) =
                        make_float2(c[mf][nf][0] + bv0, c[mf][nf][1] + bv1);
                    *reinterpret_cast<float2*>(&outp[(size_t)(row + 8) * N + col]) =
                        make_float2(c[mf][nf][2] + bv0, c[mf][nf][3] + bv1);
                }
            }
        }
    } else {
        // transpose through smem, then bf16x2-packed coalesced rows
        float* Cs = smem;
        #pragma unroll
        for (int mf = 0; mf < 4; mf++) {
            int m = mw * 64 + mf * 16 + g;
            #pragma unroll
            for (int nf = 0; nf < 4; nf++) {
                int ncol = nw * 32 + nf * 8 + 2 * tig;
                Cs[ncol * SC + m]           = c[mf][nf][0];
                Cs[(ncol + 1) * SC + m]     = c[mf][nf][1];
                Cs[ncol * SC + m + 8]       = c[mf][nf][2];
                Cs[(ncol + 1) * SC + m + 8] = c[mf][nf][3];
            }
        }
        __syncthreads();
        #pragma unroll
        for (int i = 0; i < 16; i++) {
            int q = tid + i * 256;           // 0..4095
            int nrow = q >> 5, m4 = (q & 31) * 4;
            int col = n0 + nrow;
            if (col < N) {
                float bv = bias[col];
                float4 v = *reinterpret_cast<const float4*>(&Cs[nrow * SC + m4]);
                uint2 p;
                p.x = pack_bf16(v.y + bv, v.x + bv);
                p.y = pack_bf16(v.w + bv, v.z + bv);
                *reinterpret_cast<uint2*>(&g_vT2[(size_t)col * 64 + m4 / 2]) = p;
            }
        }
    }
}

// ---------------- kernel 4: out += SLM_SCALE * gather-sum (bf16 vT) ---------
#define GTS 32
__global__ void __launch_bounds__(128)
gather_add_kernel(const int* __restrict__ sl_idx,
                  const float* __restrict__ sl_w,
                  float* __restrict__ outp) {
    __shared__ int   sidx[GTS * K_];
    __shared__ float swt [GTS * K_];
    __shared__ float sout[M_ * (GTS + 1)];

    int tid = threadIdx.x;
    int s0 = blockIdx.x * GTS;

    for (int e = tid; e < GTS * K_; e += 128) {
        size_t gg = (size_t)s0 * K_ + e;
        bool ok = (s0 + e / K_) < S_;
        sidx[e] = ok ? sl_idx[gg] : 0;
        swt[e]  = ok ? sl_w[gg]   : 0.f;
    }
    __syncthreads();

    int r2   = tid & 63;          // row pair: rows 2*r2, 2*r2+1
    int half = tid >> 6;          // s range half
    const uint32_t* vp = g_vT2 + r2;

    for (int si = 0; si < GTS / 2; si++) {
        int s = half * (GTS / 2) + si;
        const int*   ip = &sidx[s * K_];
        const float* wp = &swt [s * K_];
        float a0 = 0.f, b0 = 0.f, a1 = 0.f, b1 = 0.f;
        float a2 = 0.f, b2 = 0.f, a3 = 0.f, b3 = 0.f;
        #pragma unroll
        for (int k = 0; k < K_; k += 4) {
            uint32_t u0 = vp[(size_t)ip[k + 0] * 64];
            uint32_t u1 = vp[(size_t)ip[k + 1] * 64];
            uint32_t u2 = vp[(size_t)ip[k + 2] * 64];
            uint32_t u3 = vp[(size_t)ip[k + 3] * 64];
            float w0 = wp[k], w1 = wp[k + 1], w2 = wp[k + 2], w3 = wp[k + 3];
            a0 += w0 * __uint_as_float(u0 << 16);
            b0 += w0 * __uint_as_float(u0 & 0xffff0000u);
            a1 += w1 * __uint_as_float(u1 << 16);
            b1 += w1 * __uint_as_float(u1 & 0xffff0000u);
            a2 += w2 * __uint_as_float(u2 << 16);
            b2 += w2 * __uint_as_float(u2 & 0xffff0000u);
            a3 += w3 * __uint_as_float(u3 << 16);
            b3 += w3 * __uint_as_float(u3 & 0xffff0000u);
        }
        sout[(2 * r2)     * (GTS + 1) + s] = (a0 + a1) + (a2 + a3);
        sout[(2 * r2 + 1) * (GTS + 1) + s] = (b0 + b1) + (b2 + b3);
    }
    __syncthreads();

    int warp = tid >> 5, lane = tid & 31;
    for (int r = warp; r < M_; r += 4) {
        int s = s0 + lane;
        if (s < S_) {
            size_t o = (size_t)r * S_ + s;
            outp[o] += SLM_SCALE * sout[r * (GTS + 1) + lane];
        }
    }
}

// ---------------- launch ----------------------------------------------------
extern "C" void kernel_launch(void* const* d_in, const int* in_sizes, int n_in,
                              void* d_out, int out_size) {
    const float* x     = (const float*)d_in[0];
    const float* gamma = (const float*)d_in[1];
    const float* beta  = (const float*)d_in[2];
    const float* W1    = (const float*)d_in[3];
    const float* b1    = (const float*)d_in[4];
    const float* W2    = (const float*)d_in[5];
    const float* b2    = (const float*)d_in[6];
    const float* Wslm  = (const float*)d_in[7];
    const float* bslm  = (const float*)d_in[8];
    const float* slw   = (const float*)d_in[9];
    const int*   sli   = (const int*)d_in[10];
    float* out = (float*)d_out;

    cudaFuncSetAttribute(gemm_mma_kernel<0>,
                         cudaFuncAttributeMaxDynamicSharedMemorySize, GEMM_SMEM);
    cudaFuncSetAttribute(gemm_mma_kernel<1>,
                         cudaFuncAttributeMaxDynamicSharedMemorySize, GEMM_SMEM);

    bn_stats_kernel<<<L_, 256>>>(x, gamma, beta);
    h_kernel<<<L_, 512>>>(x, W1, b1);
    gemm_mma_kernel<1><<<(V_ + NBLK - 1) / NBLK, 256, GEMM_SMEM>>>(Wslm, bslm, nullptr, V_);
    gemm_mma_kernel<0><<<(S_ + NBLK - 1) / NBLK, 256, GEMM_SMEM>>>(W2, b2, out, S_);
    gather_add_kernel<<<(S_ + GTS - 1) / GTS, 128>>>(sli, slw, out);
}

// round 10
// speedup vs baseline: 2.0683x; 1.0093x over previous
#include <cuda_runtime.h>
#include <cstdint>

// Problem constants
#define B_  2
#define L_  64
#define D_  1024
#define H_  512
#define S_  50000
#define V_  40000
#define K_  32
#define M_  128            // B*L rows
#define SLM_SCALE 0.1f
#define BN_EPS 1e-5f

// ---------------- scratch (device globals; no allocation allowed) ----------
__device__ float g_scale[L_];
__device__ float g_shift[L_];
__device__ float g_h[M_ * H_];                    // 256 KB, tf32-rounded
__device__ uint32_t g_vT2[(size_t)V_ * 64];       // 10.24 MB: pair(row j, row j+64)

// ---------------- helpers ---------------------------------------------------
__device__ __forceinline__ uint32_t smem_u32(const void* p) {
    uint32_t a;
    asm("{ .reg .u64 t; cvta.to.shared.u64 t, %1; cvt.u32.u64 %0, t; }"
        : "=r"(a) : "l"(p));
    return a;
}
__device__ __forceinline__ float rna_tf32(float x) {
    uint32_t r;
    asm("cvt.rna.tf32.f32 %0, %1;" : "=r"(r) : "f"(x));
    return __uint_as_float(r);
}
__device__ __forceinline__ uint32_t rna_tf32_u(float x) {
    uint32_t r;
    asm("cvt.rna.tf32.f32 %0, %1;" : "=r"(r) : "f"(x));
    return r;
}
__device__ __forceinline__ uint32_t pack_bf16(float hi, float lo) {
    uint32_t r;
    asm("cvt.rn.bf16x2.f32 %0, %1, %2;" : "=r"(r) : "f"(hi), "f"(lo));
    return r;
}
__device__ __forceinline__ float bf_lo(uint32_t u) { return __uint_as_float(u << 16); }
__device__ __forceinline__ float bf_hi(uint32_t u) { return __uint_as_float(u & 0xffff0000u); }

__device__ __forceinline__ void cp16(uint32_t dst, const void* src) {
    asm volatile("cp.async.cg.shared.global [%0], [%1], 16;"
                 :: "r"(dst), "l"(src));
}
__device__ __forceinline__ void cp16z(uint32_t dst, const void* src, int sz) {
    asm volatile("cp.async.cg.shared.global [%0], [%1], 16, %2;"
                 :: "r"(dst), "l"(src), "r"(sz));
}
__device__ __forceinline__ void mma_tf32(float& c0, float& c1, float& c2, float& c3,
                                         uint32_t a0, uint32_t a1, uint32_t a2, uint32_t a3,
                                         uint32_t b0, uint32_t b1) {
    asm volatile("mma.sync.aligned.m16n8k8.row.col.f32.tf32.tf32.f32 "
                 "{%0,%1,%2,%3}, {%4,%5,%6,%7}, {%8,%9}, {%0,%1,%2,%3};"
                 : "+f"(c0), "+f"(c1), "+f"(c2), "+f"(c3)
                 : "r"(a0), "r"(a1), "r"(a2), "r"(a3), "r"(b0), "r"(b1));
}

// ---------------- kernel 1: BN stats per channel l --------------------------
__global__ void bn_stats_kernel(const float* __restrict__ x,
                                const float* __restrict__ gamma,
                                const float* __restrict__ beta) {
    int l = blockIdx.x;
    int tid = threadIdx.x;
    const float* r0 = x + (size_t)l * D_;
    const float* r1 = x + (size_t)(L_ + l) * D_;
    float s = 0.f, ss = 0.f;
    for (int d = tid; d < D_; d += blockDim.x) {
        float a = r0[d], b = r1[d];
        s  += a + b;
        ss += a * a + b * b;
    }
    __shared__ float sh_s[8], sh_ss[8];
    #pragma unroll
    for (int o = 16; o; o >>= 1) {
        s  += __shfl_down_sync(0xffffffffu, s,  o);
        ss += __shfl_down_sync(0xffffffffu, ss, o);
    }
    int w = tid >> 5;
    if ((tid & 31) == 0) { sh_s[w] = s; sh_ss[w] = ss; }
    __syncthreads();
    if (tid == 0) {
        float S = 0.f, SS = 0.f;
        #pragma unroll
        for (int i = 0; i < 8; i++) { S += sh_s[i]; SS += sh_ss[i]; }
        float inv_n = 1.0f / (2.0f * D_);
        float mean = S * inv_n;
        float var  = SS * inv_n - mean * mean;
        float sc = gamma[l] * rsqrtf(var + BN_EPS);
        g_scale[l] = sc;
        g_shift[l] = beta[l] - mean * sc;
    }
}

// ---------------- kernel 2: h = relu(xn @ W1 + b1), tf32-rounded ------------
// grid (L_, 2): one block per (l, batch) -> 128 blocks
__global__ void h_kernel(const float* __restrict__ x,
                         const float* __restrict__ W1,
                         const float* __restrict__ b1) {
    int l = blockIdx.x, bb = blockIdx.y;
    int j = threadIdx.x;   // 0..511
    __shared__ float xs[D_];
    float sc = g_scale[l], sh = g_shift[l];
    const float* r = x + (size_t)(bb * L_ + l) * D_;
    for (int d = j; d < D_; d += blockDim.x)
        xs[d] = r[d] * sc + sh;
    __syncthreads();
    float a = b1[j];
    #pragma unroll 8
    for (int d = 0; d < D_; d++)
        a += xs[d] * W1[(size_t)d * H_ + j];
    g_h[(size_t)(bb * L_ + l) * H_ + j] = rna_tf32(fmaxf(a, 0.f));
}

// ---------------- GEMM tiling constants -------------------------------------
#define NBLK 128
#define KC   32
#define SA   36                 // A smem stride (floats)
#define SBr  136                // B smem stride (floats)
#define A_SZ (128 * SA)         // 4608 floats
#define B_SZ (KC * SBr)         // 4352 floats
#define PAIR (A_SZ + B_SZ)      // 8960 floats
#define PIPE_F (2 * PAIR)       // 17920 floats
#define SC   132                // transpose stride (floats, gemm_v)
#define CYP  133                // Cy stride (odd -> conflict-free gather RMW)

// ---------------- GEMM mainloop (shared by both kernels) --------------------
struct GemmCtx {
    int tid, wid, lane, mw, nw, g, tig, n0;
};

template <typename PRE>
__device__ __forceinline__ void gemm_mainloop(
        float* smem, uint32_t sbase, const float* __restrict__ Wmat, int N,
        const GemmCtx& t, float c[4][4][4], PRE prefetch_extra) {
    auto stage = [&](int it, int buf) {
        int k0 = it * KC;
        uint32_t a_s = sbase + (uint32_t)(buf * PAIR) * 4u;
        uint32_t b_s = a_s + (uint32_t)A_SZ * 4u;
        #pragma unroll
        for (int i = 0; i < 4; i++) {
            int q = t.tid + i * 256;             // 0..1023
            int row = q >> 3, c4 = q & 7;
            cp16(a_s + (uint32_t)(row * SA + c4 * 4) * 4u,
                 &g_h[(size_t)row * H_ + k0 + c4 * 4]);
        }
        #pragma unroll
        for (int i = 0; i < 4; i++) {
            int q = t.tid + i * 256;             // 0..1023
            int kr = q >> 5, c4 = q & 31;
            int col = t.n0 + c4 * 4;
            cp16z(b_s + (uint32_t)(kr * SBr + c4 * 4) * 4u,
                  Wmat + (size_t)(k0 + kr) * N + col,
                  (col < N) ? 16 : 0);
        }
    };

    prefetch_extra();          // joins stage-0 commit group
    stage(0, 0);
    asm volatile("cp.async.commit_group;" ::: "memory");

    const int ITER = H_ / KC;                    // 16
    for (int it = 0; it < ITER; ++it) {
        int buf = it & 1;
        if (it + 1 < ITER) {
            stage(it + 1, buf ^ 1);
            asm volatile("cp.async.commit_group;" ::: "memory");
            asm volatile("cp.async.wait_group 1;" ::: "memory");
        } else {
            asm volatile("cp.async.wait_group 0;" ::: "memory");
        }
        __syncthreads();

        const float* Af = smem + buf * PAIR;
        const float* Bf = Af + A_SZ;

        #pragma unroll
        for (int ks = 0; ks < 4; ks++) {
            uint32_t a[4][4], b[4][2];
            int kc = ks * 8 + t.tig;
            #pragma unroll
            for (int mf = 0; mf < 4; mf++) {
                int r = t.mw * 64 + mf * 16 + t.g;
                a[mf][0] = __float_as_uint(Af[r * SA + kc]);
                a[mf][1] = __float_as_uint(Af[(r + 8) * SA + kc]);
                a[mf][2] = __float_as_uint(Af[r * SA + kc + 4]);
                a[mf][3] = __float_as_uint(Af[(r + 8) * SA + kc + 4]);
            }
            #pragma unroll
            for (int nf = 0; nf < 4; nf++) {
                int ncol = t.nw * 32 + nf * 8 + t.g;
                b[nf][0] = rna_tf32_u(Bf[kc * SBr + ncol]);
                b[nf][1] = rna_tf32_u(Bf[(kc + 4) * SBr + ncol]);
            }
            #pragma unroll
            for (int mf = 0; mf < 4; mf++)
                #pragma unroll
                for (int nf = 0; nf < 4; nf++)
                    mma_tf32(c[mf][nf][0], c[mf][nf][1], c[mf][nf][2], c[mf][nf][3],
                             a[mf][0], a[mf][1], a[mf][2], a[mf][3],
                             b[nf][0], b[nf][1]);
        }
        __syncthreads();
    }
}

struct NoPrefetch {
    __device__ __forceinline__ void operator()() const {}
};

// ---------------- kernel 3: v-GEMM -> g_vT2 (bf16 pairs (j, j+64)) ----------
#define GEMMV_SMEM (PIPE_F * 4)   // 71680 B

__global__ void __launch_bounds__(256, 2)
gemm_v_kernel(const float* __restrict__ Wmat,
              const float* __restrict__ bias, int N) {
    extern __shared__ float smem[];
    const uint32_t sbase = smem_u32(smem);
    GemmCtx t;
    t.tid = threadIdx.x; t.wid = t.tid >> 5; t.lane = t.tid & 31;
    t.mw = t.wid >> 2; t.nw = t.wid & 3;
    t.g = t.lane >> 2; t.tig = t.lane & 3;
    t.n0 = blockIdx.x * NBLK;

    float c[4][4][4];
    #pragma unroll
    for (int mf = 0; mf < 4; mf++)
        #pragma unroll
        for (int nf = 0; nf < 4; nf++)
            #pragma unroll
            for (int i = 0; i < 4; i++) c[mf][nf][i] = 0.f;

    gemm_mainloop(smem, sbase, Wmat, N, t, c, NoPrefetch{});

    // transpose through smem, pack (row j, row j+64) into bf16x2
    float* Cs = smem;
    #pragma unroll
    for (int mf = 0; mf < 4; mf++) {
        int m = t.mw * 64 + mf * 16 + t.g;
        #pragma unroll
        for (int nf = 0; nf < 4; nf++) {
            int ncol = t.nw * 32 + nf * 8 + 2 * t.tig;
            Cs[ncol * SC + m]           = c[mf][nf][0];
            Cs[(ncol + 1) * SC + m]     = c[mf][nf][1];
            Cs[ncol * SC + m + 8]       = c[mf][nf][2];
            Cs[(ncol + 1) * SC + m + 8] = c[mf][nf][3];
        }
    }
    __syncthreads();
    #pragma unroll
    for (int i = 0; i < 16; i++) {
        int q = t.tid + i * 256;          // 0..4095
        int jp = (q & 31) * 2;            // pair row 0..62 (even)
        int col = t.n0 + (q >> 5);
        if (col < N) {
            float bv = bias[col];
            float2 lo2 = *reinterpret_cast<const float2*>(&Cs[(q >> 5) * SC + jp]);
            float2 hi2 = *reinterpret_cast<const float2*>(&Cs[(q >> 5) * SC + jp + 64]);
            uint2 p;
            p.x = pack_bf16(hi2.x + bv, lo2.x + bv);   // rows (jp, jp+64)
            p.y = pack_bf16(hi2.y + bv, lo2.y + bv);   // rows (jp+1, jp+65)
            *reinterpret_cast<uint2*>(&g_vT2[(size_t)col * 64 + jp]) = p;
        }
    }
}

// ---------------- kernel 4: fused y-GEMM + gather + store -------------------
// smem layout: [0, PIPE_F) pipeline (phase 2 reuses [0, 128*CYP) as Cy),
//              [PIPE_F, +4096) sidx (int), [PIPE_F+4096, +4096) swt (float)
#define SIDX_F PIPE_F
#define SWT_F  (PIPE_F + 4096)
#define FUSED_SMEM ((PIPE_F + 8192) * 4)   // 104448 B

struct IdxPrefetch {
    uint32_t sbase;
    int tid, n0;
    const int* sl_idx;
    const float* sl_w;
    __device__ __forceinline__ void operator()() const {
        #pragma unroll
        for (int i = 0; i < 4; i++) {
            int q = tid + i * 256;        // 0..1023
            int e = q * 4;                // element offset (4 per cp16)
            int ok = (n0 + (e >> 5)) < S_ ? 16 : 0;
            cp16z(sbase + (uint32_t)(SIDX_F + e) * 4u,
                  sl_idx + (size_t)n0 * K_ + e, ok);
            cp16z(sbase + (uint32_t)(SWT_F + e) * 4u,
                  sl_w + (size_t)n0 * K_ + e, ok);
        }
    }
};

__global__ void __launch_bounds__(256, 2)
gemm_y_gather_kernel(const float* __restrict__ Wmat,
                     const float* __restrict__ bias,
                     const int* __restrict__ sl_idx,
                     const float* __restrict__ sl_w,
                     float* __restrict__ outp) {
    extern __shared__ float smem[];
    const uint32_t sbase = smem_u32(smem);
    GemmCtx t;
    t.tid = threadIdx.x; t.wid = t.tid >> 5; t.lane = t.tid & 31;
    t.mw = t.wid >> 2; t.nw = t.wid & 3;
    t.g = t.lane >> 2; t.tig = t.lane & 3;
    t.n0 = blockIdx.x * NBLK;
    int tid = t.tid, n0 = t.n0;

    float c[4][4][4];
    #pragma unroll
    for (int mf = 0; mf < 4; mf++)
        #pragma unroll
        for (int nf = 0; nf < 4; nf++)
            #pragma unroll
            for (int i = 0; i < 4; i++) c[mf][nf][i] = 0.f;

    IdxPrefetch pre{sbase, tid, n0, sl_idx, sl_w};
    gemm_mainloop(smem, sbase, Wmat, S_, t, c, pre);

    // ---- phase 2: scatter frags to Cy ----
    float* Cy = smem;
    #pragma unroll
    for (int mf = 0; mf < 4; mf++) {
        int row = t.mw * 64 + mf * 16 + t.g;
        #pragma unroll
        for (int nf = 0; nf < 4; nf++) {
            int cl = t.nw * 32 + nf * 8 + 2 * t.tig;
            Cy[row * CYP + cl]           = c[mf][nf][0];
            Cy[row * CYP + cl + 1]       = c[mf][nf][1];
            Cy[(row + 8) * CYP + cl]     = c[mf][nf][2];
            Cy[(row + 8) * CYP + cl + 1] = c[mf][nf][3];
        }
    }
    __syncthreads();

    // ---- phase 3: gather into Cy ----
    {
        const int*   ipb = reinterpret_cast<const int*>(smem + SIDX_F);
        const float* wpb = smem + SWT_F;
        int r2 = tid & 63;            // rows r2, r2+64
        int quarter = tid >> 6;       // s range [32q, 32q+32)
        const uint32_t* vp = g_vT2 + r2;

        for (int si = 0; si < 32; si++) {
            int s = quarter * 32 + si;
            const int*   ip = ipb + s * K_;
            const float* wp = wpb + s * K_;
            float a0 = 0.f, a1 = 0.f, a2 = 0.f, a3 = 0.f;
            float b0 = 0.f, b1 = 0.f, b2 = 0.f, b3 = 0.f;
            #pragma unroll
            for (int k = 0; k < K_; k += 8) {
                uint32_t u0 = vp[(size_t)ip[k + 0] * 64];
                uint32_t u1 = vp[(size_t)ip[k + 1] * 64];
                uint32_t u2 = vp[(size_t)ip[k + 2] * 64];
                uint32_t u3 = vp[(size_t)ip[k + 3] * 64];
                uint32_t u4 = vp[(size_t)ip[k + 4] * 64];
                uint32_t u5 = vp[(size_t)ip[k + 5] * 64];
                uint32_t u6 = vp[(size_t)ip[k + 6] * 64];
                uint32_t u7 = vp[(size_t)ip[k + 7] * 64];
                float w0 = wp[k + 0], w1 = wp[k + 1], w2 = wp[k + 2], w3 = wp[k + 3];
                float w4 = wp[k + 4], w5 = wp[k + 5], w6 = wp[k + 6], w7 = wp[k + 7];
                a0 += w0 * bf_lo(u0); b0 += w0 * bf_hi(u0);
                a1 += w1 * bf_lo(u1); b1 += w1 * bf_hi(u1);
                a2 += w2 * bf_lo(u2); b2 += w2 * bf_hi(u2);
                a3 += w3 * bf_lo(u3); b3 += w3 * bf_hi(u3);
                a0 += w4 * bf_lo(u4); b0 += w4 * bf_hi(u4);
                a1 += w5 * bf_lo(u5); b1 += w5 * bf_hi(u5);
                a2 += w6 * bf_lo(u6); b2 += w6 * bf_hi(u6);
                a3 += w7 * bf_lo(u7); b3 += w7 * bf_hi(u7);
            }
            Cy[r2 * CYP + s]        += SLM_SCALE * ((a0 + a1) + (a2 + a3));
            Cy[(r2 + 64) * CYP + s] += SLM_SCALE * ((b0 + b1) + (b2 + b3));
        }
    }
    __syncthreads();

    // ---- phase 4: coalesced store (single write of out) ----
    #pragma unroll
    for (int i = 0; i < 16; i++) {
        int q = tid + i * 256;            // 0..4095
        int row = q >> 5, c4 = (q & 31) * 4;
        int col = n0 + c4;
        if (col < S_) {                   // S % 4 == 0
            float4 bv = *reinterpret_cast<const float4*>(bias + col);
            float4 o;
            o.x = Cy[row * CYP + c4 + 0] + bv.x;
            o.y = Cy[row * CYP + c4 + 1] + bv.y;
            o.z = Cy[row * CYP + c4 + 2] + bv.z;
            o.w = Cy[row * CYP + c4 + 3] + bv.w;
            *reinterpret_cast<float4*>(&outp[(size_t)row * S_ + col]) = o;
        }
    }
}

// ---------------- launch ----------------------------------------------------
extern "C" void kernel_launch(void* const* d_in, const int* in_sizes, int n_in,
                              void* d_out, int out_size) {
    const float* x     = (const float*)d_in[0];
    const float* gamma = (const float*)d_in[1];
    const float* beta  = (const float*)d_in[2];
    const float* W1    = (const float*)d_in[3];
    const float* b1    = (const float*)d_in[4];
    const float* W2    = (const float*)d_in[5];
    const float* b2    = (const float*)d_in[6];
    const float* Wslm  = (const float*)d_in[7];
    const float* bslm  = (const float*)d_in[8];
    const float* slw   = (const float*)d_in[9];
    const int*   sli   = (const int*)d_in[10];
    float* out = (float*)d_out;

    cudaFuncSetAttribute(gemm_v_kernel,
                         cudaFuncAttributeMaxDynamicSharedMemorySize, GEMMV_SMEM);
    cudaFuncSetAttribute(gemm_y_gather_kernel,
                         cudaFuncAttributeMaxDynamicSharedMemorySize, FUSED_SMEM);

    bn_stats_kernel<<<L_, 256>>>(x, gamma, beta);
    h_kernel<<<dim3(L_, 2), 512>>>(x, W1, b1);
    gemm_v_kernel<<<(V_ + NBLK - 1) / NBLK, 256, GEMMV_SMEM>>>(Wslm, bslm, V_);
    gemm_y_gather_kernel<<<(S_ + NBLK - 1) / NBLK, 256, FUSED_SMEM>>>(
        W2, b2, sli, slw, out);
}